// round 4
// baseline (speedup 1.0000x reference)
#include <cuda_runtime.h>
#include <cstdint>

#define BB 2
#define CC 256
#define HH 128
#define WW 128
#define H2 256
#define W2 256
#define PLANE (HH * WW)

#define CPG 32        // channels per carafe block
#define STAGE 4       // channels per pipeline stage
#define NS (CPG / STAGE)
#define RSTR 132      // padded smem row stride (floats)
#define CHS (4 * RSTR + 4)

#define MG 16         // mean partial groups

// scratch (no allocations allowed)
__device__ float g_part[BB * MG * PLANE];
__device__ float g_mean[BB * PLANE];
__device__ float g_kern[BB * 9 * H2 * W2];

typedef unsigned long long ull;

// ---------------------------------------------------------------------------
// cp.async helpers
// ---------------------------------------------------------------------------
__device__ __forceinline__ void cp_async16(uint32_t dst_smem, const void* src, int src_sz) {
    asm volatile("cp.async.cg.shared.global [%0], [%1], 16, %2;\n"
                 :: "r"(dst_smem), "l"(src), "r"(src_sz));
}
__device__ __forceinline__ void cp_commit() {
    asm volatile("cp.async.commit_group;\n");
}
template <int N>
__device__ __forceinline__ void cp_wait() {
    asm volatile("cp.async.wait_group %0;\n" :: "n"(N));
}

// ---------------------------------------------------------------------------
// Kernel A1: partial channel sums (CC/MG channels per slice, float4 pixels)
// ---------------------------------------------------------------------------
__global__ void mean1_kernel(const float* __restrict__ x) {
    int t  = threadIdx.x;
    int p4 = blockIdx.x * 256 + t;
    int cg = blockIdx.y;
    int b  = blockIdx.z;
    const float4* xp = (const float4*)x
                     + (size_t)(b * CC + cg * (CC / MG)) * (PLANE / 4) + p4;
    float4 s = make_float4(0.f, 0.f, 0.f, 0.f);
#pragma unroll
    for (int c = 0; c < CC / MG; ++c) {
        float4 v = xp[(size_t)c * (PLANE / 4)];
        s.x += v.x; s.y += v.y; s.z += v.z; s.w += v.w;
    }
    ((float4*)g_part)[((size_t)(b * MG + cg)) * (PLANE / 4) + p4] = s;
}

// ---------------------------------------------------------------------------
// Kernel A2: combine partials -> mean
// ---------------------------------------------------------------------------
__global__ void mean2_kernel() {
    int idx = blockIdx.x * 256 + threadIdx.x;
    int b   = idx / (PLANE / 4);
    int p4  = idx % (PLANE / 4);
    float4 s = make_float4(0.f, 0.f, 0.f, 0.f);
#pragma unroll
    for (int g = 0; g < MG; ++g) {
        float4 v = ((const float4*)g_part)[((size_t)(b * MG + g)) * (PLANE / 4) + p4];
        s.x += v.x; s.y += v.y; s.z += v.z; s.w += v.w;
    }
    const float sc = 1.0f / CC;
    s.x *= sc; s.y *= sc; s.z *= sc; s.w *= sc;
    ((float4*)g_mean)[(size_t)b * (PLANE / 4) + p4] = s;
}

// ---------------------------------------------------------------------------
// Kernel B: fused offset-conv + tanh + center + inverse-distance kernels +
//           grad gating + softmax  ->  g_kern[b,k,y,x]
// ---------------------------------------------------------------------------
__device__ __forceinline__ float fast_tanh(float x) {
    float e = __expf(2.0f * x);
    return __fdividef(e - 1.0f, e + 1.0f);
}

__global__ void kern_kernel(const float* __restrict__ Woff,
                            const float* __restrict__ boff) {
    __shared__ float sW[50];
    __shared__ float sb[2];
    int t = threadIdx.x;
    if (t < 50) sW[t] = Woff[t];
    if (t < 2) sb[t] = boff[t];
    __syncthreads();

    int idx = blockIdx.x * blockDim.x + t;
    int xq = idx & (W2 - 1);
    int y  = (idx >> 8) & (H2 - 1);
    int b  = idx >> 16;

    const float* m = g_mean + b * PLANE;

    float a0 = 0.f, a1 = 0.f;
#pragma unroll
    for (int u = 0; u < 5; ++u) {
        int Y = y - 2 + u;
        if (Y < 0 || Y >= H2) continue;
        int hh = Y >> 1;
#pragma unroll
        for (int v = 0; v < 5; ++v) {
            int X = xq - 2 + v;
            if (X < 0 || X >= W2) continue;
            float mv = m[hh * WW + (X >> 1)];
            a0 = fmaf(mv, sW[u * 5 + v], a0);
            a1 = fmaf(mv, sW[25 + u * 5 + v], a1);
        }
    }
    float s0 = ((xq & 1) ? 0.25f : -0.25f) + 0.25f * fast_tanh(a0 + sb[0]);
    float s1 = ((y  & 1) ? 0.25f : -0.25f) + 0.25f * fast_tanh(a1 + sb[1]);

    int hh = y >> 1, ww = xq >> 1;
    float mc = m[hh * WW + ww];

    float logit[9];
    float mx = -1e30f;
#pragma unroll
    for (int k = 0; k < 9; ++k) {
        int di = k / 3 - 1;
        int dj = k % 3 - 1;
        int hn = hh + di, wn = ww + dj;
        float pm = (hn >= 0 && hn < HH && wn >= 0 && wn < WW)
                   ? m[hn * WW + wn] : 0.f;
        float d = pm - mc;
        float e0 = s0 - (float)dj;
        float e1 = s1 - (float)di;
        float d2 = fmaf(e0, e0, fmaf(e1, e1, 0.2f));
        float kv = __fdividef(1.f, fmaf(d, d, 1.f) * d2);
        logit[k] = kv;
        mx = fmaxf(mx, kv);
    }
    float ev[9];
    float sum = 0.f;
#pragma unroll
    for (int k = 0; k < 9; ++k) { ev[k] = __expf(logit[k] - mx); sum += ev[k]; }
    float inv = __fdividef(1.f, sum);
#pragma unroll
    for (int k = 0; k < 9; ++k)
        g_kern[((b * 9 + k) * H2 + y) * W2 + xq] = ev[k] * inv;
}

// ---------------------------------------------------------------------------
// Kernel C: CARAFE apply.
// Block = (32-channel group, 2-input-row stripe, batch). 512 threads.
// Thread = ONE output row of a cell (1x2 pixels) -> only 18 weight regs.
// Lane pairing: lane = (w&15)*2 + p, so the two threads sharing a 3x3 patch
// sit in the same warp and their LDS broadcast-merge (no extra smem traffic).
// x planes streamed via cp.async double buffer; packed f32x2 FFMA.
// ---------------------------------------------------------------------------
__global__ void __launch_bounds__(512, 3)
carafe_kernel(const float* __restrict__ x, float* __restrict__ out) {
    __shared__ __align__(16) float xs[2][STAGE][CHS];

    int b  = blockIdx.z;
    int h0 = blockIdx.y * 2;
    int c0 = blockIdx.x * CPG;
    int t  = threadIdx.x;

    // decode: lane = (w&15)*2 + p ; warp = r*8 + (w>>4)
    int p   = t & 1;
    int w   = (((t >> 5) & 7) << 4) | ((t >> 1) & 15);
    int r   = t >> 8;                 // 0..1 local input row
    int h   = h0 + r;
    int y   = 2 * h + p;              // output row

    // hoist 9 weight pairs for this 1x2 output cell (packed f32x2)
    const ull* kp = (const ull*)(g_kern + (size_t)b * 9 * H2 * W2);
    ull wk[9];
#pragma unroll
    for (int k = 0; k < 9; ++k)
        wk[k] = kp[((size_t)k * H2 + y) * (W2 / 2) + w];

    // zero halo cells once (both buffers)
    if (t < 64) {
        int bufi = t >> 5, lt = t & 31;
        int ch = lt >> 3, rem = lt & 7, row = rem >> 1, side = rem & 1;
        xs[bufi][ch][row * RSTR + (side ? RSTR : 3)] = 0.f;
    }

    const float* xb = x + (size_t)b * CC * PLANE;

    // stage loader via cp.async: 4 ch x 4 rows x 32 float4 = 512 copies
    auto load_stage = [&](int s, int buf) {
        int cb   = c0 + s * STAGE;
        int ch   = t >> 7;
        int rem  = t & 127;
        int row  = rem >> 5;
        int col4 = rem & 31;
        int grow = h0 - 1 + row;
        int ok   = (grow >= 0 && grow < HH);
        const float* src = xb + (size_t)(cb + ch) * PLANE
                         + (ok ? grow : 0) * WW + (col4 << 2);
        uint32_t dst = (uint32_t)__cvta_generic_to_shared(
            &xs[buf][ch][row * RSTR + 4 + (col4 << 2)]);
        cp_async16(dst, src, ok ? 16 : 0);
    };

    load_stage(0, 0);
    cp_commit();

#pragma unroll 1
    for (int s = 0; s < NS; ++s) {
        int buf = s & 1;
        __syncthreads();
        if (s + 1 < NS) { load_stage(s + 1, buf ^ 1); cp_commit(); cp_wait<1>(); }
        else           { cp_wait<0>(); }
        __syncthreads();

        int cbase = c0 + s * STAGE;
#pragma unroll
        for (int ch = 0; ch < STAGE; ++ch) {
            const float* base = &xs[buf][ch][r * RSTR + 4 + w];
            ull acc = 0ull;
#pragma unroll
            for (int di = 0; di < 3; ++di) {
                const float* rp = base + di * RSTR;
                float xv[3] = { rp[-1], rp[0], rp[1] };
#pragma unroll
                for (int dj = 0; dj < 3; ++dj) {
                    int k = di * 3 + dj;
                    unsigned vu = __float_as_uint(xv[dj]);
                    ull vv;
                    asm("mov.b64 %0, {%1, %2};" : "=l"(vv) : "r"(vu), "r"(vu));
                    asm("fma.rn.f32x2 %0, %1, %2, %0;"
                        : "+l"(acc) : "l"(wk[k]), "l"(vv));
                }
            }
            float2* op = (float2*)(out + (((size_t)(b * CC + cbase + ch)) * H2
                                          + y) * W2);
            op[w] = *(float2*)&acc;
        }
    }
}

extern "C" void kernel_launch(void* const* d_in, const int* in_sizes, int n_in,
                              void* d_out, int out_size) {
    const float* x    = (const float*)d_in[0];
    const float* Woff = (const float*)d_in[1];
    const float* boff = (const float*)d_in[2];
    float* out = (float*)d_out;

    mean1_kernel<<<dim3(PLANE / 4 / 256, MG, BB), 256>>>(x);
    mean2_kernel<<<(BB * PLANE / 4) / 256, 256>>>();
    kern_kernel<<<(BB * H2 * W2) / 256, 256>>>(Woff, boff);
    carafe_kernel<<<dim3(CC / CPG, HH / 2, BB), 512>>>(x, out);
}

// round 5
// speedup vs baseline: 1.1341x; 1.1341x over previous
#include <cuda_runtime.h>
#include <cstdint>

#define BB 2
#define CC 256
#define HH 128
#define WW 128
#define H2 256
#define W2 256
#define PLANE (HH * WW)

#define CPG 64        // channels per carafe block -> 512 blocks = 1 wave
#define STAGE 4       // channels per pipeline stage
#define NS (CPG / STAGE)
#define NBUF 3        // cp.async ring depth
#define RSTR 132      // padded smem row stride (floats)
#define CHS (4 * RSTR + 4)

#define MG 16         // mean partial groups

// scratch (no allocations allowed)
__device__ float g_part[BB * MG * PLANE];
__device__ float g_mean[BB * PLANE];
__device__ float g_kern[BB * 9 * H2 * W2];

typedef unsigned long long ull;

// ---------------------------------------------------------------------------
// cp.async helpers
// ---------------------------------------------------------------------------
__device__ __forceinline__ void cp_async16(uint32_t dst_smem, const void* src, int src_sz) {
    asm volatile("cp.async.cg.shared.global [%0], [%1], 16, %2;\n"
                 :: "r"(dst_smem), "l"(src), "r"(src_sz));
}
__device__ __forceinline__ void cp_commit() {
    asm volatile("cp.async.commit_group;\n");
}
template <int N>
__device__ __forceinline__ void cp_wait() {
    asm volatile("cp.async.wait_group %0;\n" :: "n"(N));
}

// ---------------------------------------------------------------------------
// Kernel A1: partial channel sums (CC/MG channels per slice, float4 pixels)
// ---------------------------------------------------------------------------
__global__ void mean1_kernel(const float* __restrict__ x) {
    int t  = threadIdx.x;
    int p4 = blockIdx.x * 256 + t;
    int cg = blockIdx.y;
    int b  = blockIdx.z;
    const float4* xp = (const float4*)x
                     + (size_t)(b * CC + cg * (CC / MG)) * (PLANE / 4) + p4;
    float4 s = make_float4(0.f, 0.f, 0.f, 0.f);
#pragma unroll
    for (int c = 0; c < CC / MG; ++c) {
        float4 v = xp[(size_t)c * (PLANE / 4)];
        s.x += v.x; s.y += v.y; s.z += v.z; s.w += v.w;
    }
    ((float4*)g_part)[((size_t)(b * MG + cg)) * (PLANE / 4) + p4] = s;
}

// ---------------------------------------------------------------------------
// Kernel A2: combine partials -> mean
// ---------------------------------------------------------------------------
__global__ void mean2_kernel() {
    int idx = blockIdx.x * 256 + threadIdx.x;
    int b   = idx / (PLANE / 4);
    int p4  = idx % (PLANE / 4);
    float4 s = make_float4(0.f, 0.f, 0.f, 0.f);
#pragma unroll
    for (int g = 0; g < MG; ++g) {
        float4 v = ((const float4*)g_part)[((size_t)(b * MG + g)) * (PLANE / 4) + p4];
        s.x += v.x; s.y += v.y; s.z += v.z; s.w += v.w;
    }
    const float sc = 1.0f / CC;
    s.x *= sc; s.y *= sc; s.z *= sc; s.w *= sc;
    ((float4*)g_mean)[(size_t)b * (PLANE / 4) + p4] = s;
}

// ---------------------------------------------------------------------------
// Kernel B: fused offset-conv + tanh + center + inverse-distance kernels +
//           grad gating + softmax (no max-sub; logits bounded in (0.19, 5])
// ---------------------------------------------------------------------------
__device__ __forceinline__ float fast_tanh(float x) {
    float e = __expf(2.0f * x);
    return __fdividef(e - 1.0f, e + 1.0f);
}

__global__ void kern_kernel(const float* __restrict__ Woff,
                            const float* __restrict__ boff) {
    __shared__ float sW[50];
    __shared__ float sb[2];
    int t = threadIdx.x;
    if (t < 50) sW[t] = Woff[t];
    if (t < 2) sb[t] = boff[t];
    __syncthreads();

    int idx = blockIdx.x * blockDim.x + t;
    int xq = idx & (W2 - 1);
    int y  = (idx >> 8) & (H2 - 1);
    int b  = idx >> 16;

    const float* m = g_mean + b * PLANE;

    float a0 = 0.f, a1 = 0.f;
#pragma unroll
    for (int u = 0; u < 5; ++u) {
        int Y = y - 2 + u;
        if (Y < 0 || Y >= H2) continue;
        int hh = Y >> 1;
#pragma unroll
        for (int v = 0; v < 5; ++v) {
            int X = xq - 2 + v;
            if (X < 0 || X >= W2) continue;
            float mv = m[hh * WW + (X >> 1)];
            a0 = fmaf(mv, sW[u * 5 + v], a0);
            a1 = fmaf(mv, sW[25 + u * 5 + v], a1);
        }
    }
    float s0 = ((xq & 1) ? 0.25f : -0.25f) + 0.25f * fast_tanh(a0 + sb[0]);
    float s1 = ((y  & 1) ? 0.25f : -0.25f) + 0.25f * fast_tanh(a1 + sb[1]);

    int hh = y >> 1, ww = xq >> 1;
    float mc = m[hh * WW + ww];

    float ev[9];
    float sum = 0.f;
#pragma unroll
    for (int k = 0; k < 9; ++k) {
        int di = k / 3 - 1;
        int dj = k % 3 - 1;
        int hn = hh + di, wn = ww + dj;
        float pm = (hn >= 0 && hn < HH && wn >= 0 && wn < WW)
                   ? m[hn * WW + wn] : 0.f;
        float d = pm - mc;
        float e0 = s0 - (float)dj;
        float e1 = s1 - (float)di;
        float d2 = fmaf(e0, e0, fmaf(e1, e1, 0.2f));
        float kv = __fdividef(1.f, fmaf(d, d, 1.f) * d2);
        ev[k] = __expf(kv);
        sum += ev[k];
    }
    float inv = __fdividef(1.f, sum);
#pragma unroll
    for (int k = 0; k < 9; ++k)
        g_kern[((b * 9 + k) * H2 + y) * W2 + xq] = ev[k] * inv;
}

// ---------------------------------------------------------------------------
// Kernel C: CARAFE apply.
// Block = (64-channel group, 2-input-row stripe, batch). 256 threads.
// Thread = one input pixel -> 2x2 output cell (R3 mapping: LDS instr count
// is the binding L1 constraint, so keep 256 threads). cp.async 3-buffer
// ring, ONE __syncthreads per stage. Packed f32x2 FFMA.
// ---------------------------------------------------------------------------
__global__ void __launch_bounds__(256, 4)
carafe_kernel(const float* __restrict__ x, float* __restrict__ out) {
    __shared__ __align__(16) float xs[NBUF][STAGE][CHS];

    int b  = blockIdx.z;
    int h0 = blockIdx.y * 2;
    int c0 = blockIdx.x * CPG;
    int t  = threadIdx.x;
    int r  = t >> 7;                  // 0..1 local input row
    int w  = t & 127;                 // input column
    int h  = h0 + r;

    // hoist the 36 softmax weights for this 2x2 output cell (packed f32x2)
    const ull* kp = (const ull*)(g_kern + (size_t)b * 9 * H2 * W2);
    ull wk0[9], wk1[9];
#pragma unroll
    for (int k = 0; k < 9; ++k) {
        wk0[k] = kp[((size_t)k * H2 + 2 * h)     * (W2 / 2) + w];
        wk1[k] = kp[((size_t)k * H2 + 2 * h + 1) * (W2 / 2) + w];
    }

    // zero halo cells once (all NBUF buffers):
    // per (buf,ch,row): left halo slot row*RSTR+3, right halo slot (row+1)*RSTR
    if (t < 32 * NBUF) {
        int bufi = t >> 5, lt = t & 31;
        int ch = lt >> 3, rem = lt & 7, row = rem >> 1, side = rem & 1;
        xs[bufi][ch][row * RSTR + (side ? RSTR : 3)] = 0.f;
    }

    const float* xb = x + (size_t)b * CC * PLANE;

    // stage loader via cp.async: 4 ch x 4 rows x 32 float4 = 512 copies
    auto load_stage = [&](int s, int buf) {
        int cb = c0 + s * STAGE;
#pragma unroll
        for (int u = 0; u < 2; ++u) {
            int lin  = u * 256 + t;
            int ch   = lin >> 7;
            int rem  = lin & 127;
            int row  = rem >> 5;
            int col4 = rem & 31;
            int grow = h0 - 1 + row;
            int ok   = (grow >= 0 && grow < HH);
            const float* src = xb + (size_t)(cb + ch) * PLANE
                             + (ok ? grow : 0) * WW + (col4 << 2);
            uint32_t dst = (uint32_t)__cvta_generic_to_shared(
                &xs[buf][ch][row * RSTR + 4 + (col4 << 2)]);
            cp_async16(dst, src, ok ? 16 : 0);
        }
    };

    // prologue: two stages in flight
    load_stage(0, 0); cp_commit();
    load_stage(1, 1); cp_commit();

#pragma unroll 1
    for (int s = 0; s < NS; ++s) {
        int buf = s % NBUF;
        // ensure stage s landed (pending may include s+1)
        if (s == NS - 1) cp_wait<0>(); else cp_wait<1>();
        __syncthreads();   // also guarantees buf (s+2)%NBUF fully consumed
        if (s + 2 < NS) { load_stage(s + 2, (s + 2) % NBUF); cp_commit(); }

        int cbase = c0 + s * STAGE;
#pragma unroll
        for (int ch = 0; ch < STAGE; ++ch) {
            const float* base = &xs[buf][ch][r * RSTR + 4 + w];
            ull acc0 = 0ull, acc1 = 0ull;
#pragma unroll
            for (int di = 0; di < 3; ++di) {
                const float* rp = base + di * RSTR;
                float xv[3] = { rp[-1], rp[0], rp[1] };
#pragma unroll
                for (int dj = 0; dj < 3; ++dj) {
                    int k = di * 3 + dj;
                    unsigned vu = __float_as_uint(xv[dj]);
                    ull vv;
                    asm("mov.b64 %0, {%1, %2};" : "=l"(vv) : "r"(vu), "r"(vu));
                    asm("fma.rn.f32x2 %0, %1, %2, %0;"
                        : "+l"(acc0) : "l"(wk0[k]), "l"(vv));
                    asm("fma.rn.f32x2 %0, %1, %2, %0;"
                        : "+l"(acc1) : "l"(wk1[k]), "l"(vv));
                }
            }
            float2* op = (float2*)(out + (((size_t)(b * CC + cbase + ch)) * H2
                                          + 2 * h) * W2);
            op[w] = *(float2*)&acc0;
            op[(W2 / 2) + w] = *(float2*)&acc1;
        }
    }
}

extern "C" void kernel_launch(void* const* d_in, const int* in_sizes, int n_in,
                              void* d_out, int out_size) {
    const float* x    = (const float*)d_in[0];
    const float* Woff = (const float*)d_in[1];
    const float* boff = (const float*)d_in[2];
    float* out = (float*)d_out;

    mean1_kernel<<<dim3(PLANE / 4 / 256, MG, BB), 256>>>(x);
    mean2_kernel<<<(BB * PLANE / 4) / 256, 256>>>();
    kern_kernel<<<(BB * H2 * W2) / 256, 256>>>(Woff, boff);
    carafe_kernel<<<dim3(CC / CPG, HH / 2, BB), 256>>>(x, out);
}